// round 1
// baseline (speedup 1.0000x reference)
#include <cuda_runtime.h>
#include <math.h>

#define BB 2
#define NN 2048
#define CC 256
#define HH 8
#define DHH 32
#define TABW (2*NN-1)
#define SCALE 0.17677669529663687f  // 1/sqrt(32)

// ---- scratch (static device globals; no allocation allowed) ----
__device__ float g_q[BB*HH*NN*DHH];
__device__ float g_k[BB*HH*NN*DHH];
__device__ float g_v[BB*HH*NN*DHH];
__device__ float g_ctx[BB*NN*CC];
__device__ float g_tab[HH*TABW];
__device__ float g_pm[HH*NN];    // pos row max
__device__ float g_pinv[HH*NN];  // 1 / pos row sumexp
__device__ float g_m[BB*HH*NN];  // patch row max (scaled scores)
__device__ float g_l[BB*HH*NN];  // patch row sumexp

// ============================================================
// 1) positional logit table: tab[h][dd], dd = d + (N-1)
// ============================================================
__global__ void pos_tab_kernel(const float* __restrict__ Wpos,
                               const float* __restrict__ bpos) {
    int idx = blockIdx.x * blockDim.x + threadIdx.x;
    if (idx >= HH * TABW) return;
    int h  = idx / TABW;
    int dd = idx % TABW;
    float d = (float)(dd - (NN - 1));
    g_tab[idx] = Wpos[h] * d + Wpos[HH + h] * fabsf(d) + bpos[h];
}

// ============================================================
// 2) per (h, i): row max (analytic, piecewise-linear) + sumexp
//    one warp per row
// ============================================================
__global__ void pos_row_kernel() {
    int w    = blockIdx.x * 8 + (threadIdx.x >> 5);
    int lane = threadIdx.x & 31;
    int h = w / NN, i = w % NN;
    const float* tab = g_tab + h * TABW;
    // window d in [i-(N-1), i] always contains 0; linear on each side of 0
    float m = fmaxf(fmaxf(tab[i], tab[i + NN - 1]), tab[NN - 1]);
    float s = 0.f;
    for (int j = lane; j < NN; j += 32)
        s += __expf(tab[i + NN - 1 - j] - m);
    #pragma unroll
    for (int o = 16; o; o >>= 1) s += __shfl_xor_sync(0xffffffffu, s, o);
    if (lane == 0) { g_pm[h*NN + i] = m; g_pinv[h*NN + i] = 1.f / s; }
}

// ============================================================
// 3) QKV projection GEMM: [4096,256] x [256,768] -> scatter q/k/v
//    64x64 tile, 256 threads, 4x4 micro
// ============================================================
__global__ void qkv_gemm_kernel(const float* __restrict__ x,
                                const float* __restrict__ Wqk,
                                const float* __restrict__ Wv) {
    __shared__ float As[16][64];
    __shared__ float Bs[16][64];
    int tid = threadIdx.x;
    int ty = tid >> 4, tx = tid & 15;
    int m0 = blockIdx.x * 64;
    int n0 = blockIdx.y * 64;
    float acc[4][4] = {};
    int arow = tid >> 2, acol = (tid & 3) * 4;
    int brow = tid >> 4, bcol = (tid & 15) * 4;

    for (int k0 = 0; k0 < 256; k0 += 16) {
        float4 av = *(const float4*)&x[(m0 + arow) * 256 + k0 + acol];
        As[acol + 0][arow] = av.x; As[acol + 1][arow] = av.y;
        As[acol + 2][arow] = av.z; As[acol + 3][arow] = av.w;
        int gc = n0 + bcol;
        float4 bv;
        if (gc < 512) bv = *(const float4*)&Wqk[(k0 + brow) * 512 + gc];
        else          bv = *(const float4*)&Wv[(k0 + brow) * 256 + gc - 512];
        *(float4*)&Bs[brow][bcol] = bv;
        __syncthreads();
        #pragma unroll
        for (int kk = 0; kk < 16; kk++) {
            float4 a = *(float4*)&As[kk][4 * ty];
            float4 b = *(float4*)&Bs[kk][4 * tx];
            float aa[4] = {a.x, a.y, a.z, a.w};
            float bb[4] = {b.x, b.y, b.z, b.w};
            #pragma unroll
            for (int i = 0; i < 4; i++)
                #pragma unroll
                for (int j = 0; j < 4; j++)
                    acc[i][j] += aa[i] * bb[j];
        }
        __syncthreads();
    }
    #pragma unroll
    for (int i = 0; i < 4; i++) {
        int m = m0 + 4 * ty + i;
        int b = m >> 11, n = m & (NN - 1);
        #pragma unroll
        for (int j = 0; j < 4; j++) {
            int c = n0 + 4 * tx + j;
            float v = acc[i][j];
            if (c < 256) {
                int h = c >> 5, d = c & 31;
                g_q[((b * HH + h) * NN + n) * DHH + d] = v;
            } else if (c < 512) {
                int cc = c - 256; int h = cc >> 5, d = cc & 31;
                g_k[((b * HH + h) * NN + n) * DHH + d] = v;
            } else {
                int cc = c - 512; int h = cc >> 5, d = cc & 31;
                g_v[((b * HH + h) * NN + n) * DHH + d] = v;
            }
        }
    }
}

// ============================================================
// 4) Pass A: patch-softmax row max + sumexp (online over key tiles)
//    block = 64 q-rows of one (b,h); 256 threads as 16x16, 4x4 micro
// ============================================================
__global__ void attn_ml_kernel() {
    __shared__ float qs[32][64];  // [d][row], pre-scaled
    __shared__ float ks[32][64];  // [d][key]
    int tid = threadIdx.x;
    int ty = tid >> 4, tx = tid & 15;
    int qt = blockIdx.x, h = blockIdx.y, b = blockIdx.z;
    int bh = b * HH + h;
    const float* qg = g_q + (bh * NN + qt * 64) * DHH;
    const float* kg = g_k + bh * NN * DHH;

    #pragma unroll
    for (int r = 0; r < 8; r++) {
        int lin = tid + r * 256;
        qs[lin & 31][lin >> 5] = qg[lin] * SCALE;
    }
    float m[4], l[4];
    #pragma unroll
    for (int i = 0; i < 4; i++) { m[i] = -1e30f; l[i] = 0.f; }

    for (int kt = 0; kt < 32; kt++) {
        __syncthreads();
        #pragma unroll
        for (int r = 0; r < 8; r++) {
            int lin = tid + r * 256;
            ks[lin & 31][lin >> 5] = kg[kt * 64 * DHH + lin];
        }
        __syncthreads();
        float s[4][4] = {};
        #pragma unroll
        for (int d = 0; d < 32; d++) {
            float4 a  = *(float4*)&qs[d][4 * ty];
            float4 bv = *(float4*)&ks[d][4 * tx];
            float aa[4] = {a.x, a.y, a.z, a.w};
            float bb[4] = {bv.x, bv.y, bv.z, bv.w};
            #pragma unroll
            for (int i = 0; i < 4; i++)
                #pragma unroll
                for (int j = 0; j < 4; j++)
                    s[i][j] += aa[i] * bb[j];
        }
        #pragma unroll
        for (int i = 0; i < 4; i++) {
            float rm = fmaxf(fmaxf(s[i][0], s[i][1]), fmaxf(s[i][2], s[i][3]));
            #pragma unroll
            for (int o = 8; o; o >>= 1) rm = fmaxf(rm, __shfl_xor_sync(0xffffffffu, rm, o));
            float mn = fmaxf(m[i], rm);
            float rs = __expf(s[i][0] - mn) + __expf(s[i][1] - mn)
                     + __expf(s[i][2] - mn) + __expf(s[i][3] - mn);
            #pragma unroll
            for (int o = 8; o; o >>= 1) rs += __shfl_xor_sync(0xffffffffu, rs, o);
            l[i] = l[i] * __expf(m[i] - mn) + rs;
            m[i] = mn;
        }
    }
    if (tx == 0) {
        #pragma unroll
        for (int i = 0; i < 4; i++) {
            int row = bh * NN + qt * 64 + 4 * ty + i;
            g_m[row] = m[i];
            g_l[row] = l[i];
        }
    }
}

// ============================================================
// 5) Pass B: combined weights + P@V -> ctx [B,N,C]
// ============================================================
__global__ void attn_out_kernel(const float* __restrict__ gating) {
    __shared__ float qs[32][64];
    __shared__ float ks[32][64];
    __shared__ float vs[64][32];
    __shared__ float pT[64][66];   // [key][row], padded
    __shared__ float ts[128];      // pos-logit slice
    __shared__ float cm[64], cl1[64], pm[64], c2[64];

    int tid = threadIdx.x;
    int ty = tid >> 4, tx = tid & 15;
    int y2 = tid >> 3, x2 = tid & 7;
    int qt = blockIdx.x, h = blockIdx.y, b = blockIdx.z;
    int bh = b * HH + h;
    int q0 = qt * 64;
    const float* qg = g_q + (bh * NN + q0) * DHH;
    const float* kg = g_k + bh * NN * DHH;
    const float* vg = g_v + bh * NN * DHH;

    #pragma unroll
    for (int r = 0; r < 8; r++) {
        int lin = tid + r * 256;
        qs[lin & 31][lin >> 5] = qg[lin] * SCALE;
    }
    if (tid < 64) {
        int grow = q0 + tid;
        float gv = 1.f / (1.f + __expf(-gating[h]));
        cm[tid]  = g_m[bh * NN + grow];
        cl1[tid] = (1.f - gv) / g_l[bh * NN + grow];
        pm[tid]  = g_pm[h * NN + grow];
        c2[tid]  = gv * g_pinv[h * NN + grow];
    }
    float acc0[4] = {}, acc1[4] = {};

    for (int kt = 0; kt < 32; kt++) {
        int k0 = kt * 64;
        __syncthreads();
        #pragma unroll
        for (int r = 0; r < 8; r++) {
            int lin = tid + r * 256;
            ks[lin & 31][lin >> 5] = kg[k0 * DHH + lin];
            ((float*)vs)[lin]      = vg[k0 * DHH + lin];
        }
        if (tid < 127) ts[tid] = g_tab[h * TABW + (q0 - k0 + 1984) + tid];
        __syncthreads();

        float s[4][4] = {};
        #pragma unroll
        for (int d = 0; d < 32; d++) {
            float4 a  = *(float4*)&qs[d][4 * ty];
            float4 bv = *(float4*)&ks[d][4 * tx];
            float aa[4] = {a.x, a.y, a.z, a.w};
            float bb[4] = {bv.x, bv.y, bv.z, bv.w};
            #pragma unroll
            for (int i = 0; i < 4; i++)
                #pragma unroll
                for (int j = 0; j < 4; j++)
                    s[i][j] += aa[i] * bb[j];
        }
        #pragma unroll
        for (int i = 0; i < 4; i++) {
            int r = 4 * ty + i;
            float c1r = cl1[r], cmr = cm[r], c2r = c2[r], pmr = pm[r];
            #pragma unroll
            for (int j = 0; j < 4; j++) {
                int jl = 4 * tx + j;
                float w = c1r * __expf(s[i][j] - cmr)
                        + c2r * __expf(ts[r - jl + 63] - pmr);
                pT[jl][r] = w;
            }
        }
        __syncthreads();
        #pragma unroll 16
        for (int j = 0; j < 64; j++) {
            float a0 = pT[j][2 * y2], a1 = pT[j][2 * y2 + 1];
            float4 bv = *(float4*)&vs[j][4 * x2];
            acc0[0] += a0 * bv.x; acc0[1] += a0 * bv.y;
            acc0[2] += a0 * bv.z; acc0[3] += a0 * bv.w;
            acc1[0] += a1 * bv.x; acc1[1] += a1 * bv.y;
            acc1[2] += a1 * bv.z; acc1[3] += a1 * bv.w;
        }
    }
    int row = q0 + 2 * y2;
    int col = h * 32 + 4 * x2;
    float* o0 = &g_ctx[(b * NN + row) * CC + col];
    *(float4*)o0        = make_float4(acc0[0], acc0[1], acc0[2], acc0[3]);
    *(float4*)(o0 + CC) = make_float4(acc1[0], acc1[1], acc1[2], acc1[3]);
}

// ============================================================
// 6) Output projection: ctx [4096,256] x W_proj [256,256] + b -> out
// ============================================================
__global__ void proj_gemm_kernel(const float* __restrict__ Wp,
                                 const float* __restrict__ bp,
                                 float* __restrict__ out) {
    __shared__ float As[16][64];
    __shared__ float Bs[16][64];
    int tid = threadIdx.x;
    int ty = tid >> 4, tx = tid & 15;
    int m0 = blockIdx.x * 64;
    int n0 = blockIdx.y * 64;
    float acc[4][4] = {};
    int arow = tid >> 2, acol = (tid & 3) * 4;
    int brow = tid >> 4, bcol = (tid & 15) * 4;

    for (int k0 = 0; k0 < 256; k0 += 16) {
        float4 av = *(const float4*)&g_ctx[(m0 + arow) * 256 + k0 + acol];
        As[acol + 0][arow] = av.x; As[acol + 1][arow] = av.y;
        As[acol + 2][arow] = av.z; As[acol + 3][arow] = av.w;
        float4 bv = *(const float4*)&Wp[(k0 + brow) * 256 + n0 + bcol];
        *(float4*)&Bs[brow][bcol] = bv;
        __syncthreads();
        #pragma unroll
        for (int kk = 0; kk < 16; kk++) {
            float4 a = *(float4*)&As[kk][4 * ty];
            float4 b = *(float4*)&Bs[kk][4 * tx];
            float aa[4] = {a.x, a.y, a.z, a.w};
            float bb[4] = {b.x, b.y, b.z, b.w};
            #pragma unroll
            for (int i = 0; i < 4; i++)
                #pragma unroll
                for (int j = 0; j < 4; j++)
                    acc[i][j] += aa[i] * bb[j];
        }
        __syncthreads();
    }
    #pragma unroll
    for (int i = 0; i < 4; i++) {
        int m = m0 + 4 * ty + i;
        #pragma unroll
        for (int j = 0; j < 4; j++) {
            int c = n0 + 4 * tx + j;
            out[m * 256 + c] = acc[i][j] + bp[c];
        }
    }
}

// ============================================================
extern "C" void kernel_launch(void* const* d_in, const int* in_sizes, int n_in,
                              void* d_out, int out_size) {
    const float* x     = (const float*)d_in[0];
    const float* Wqk   = (const float*)d_in[1];
    const float* Wv    = (const float*)d_in[2];
    const float* Wproj = (const float*)d_in[3];
    const float* bproj = (const float*)d_in[4];
    const float* Wpos  = (const float*)d_in[5];
    const float* bpos  = (const float*)d_in[6];
    const float* gate  = (const float*)d_in[7];
    float* out = (float*)d_out;

    pos_tab_kernel<<<(HH * TABW + 255) / 256, 256>>>(Wpos, bpos);
    pos_row_kernel<<<HH * NN / 8, 256>>>();
    qkv_gemm_kernel<<<dim3(BB * NN / 64, 12), 256>>>(x, Wqk, Wv);
    attn_ml_kernel<<<dim3(NN / 64, HH, BB), 256>>>();
    attn_out_kernel<<<dim3(NN / 64, HH, BB), 256>>>(gate);
    proj_gemm_kernel<<<dim3(BB * NN / 64, 4), 256>>>(Wproj, bproj, out);
}

// round 2
// speedup vs baseline: 1.0025x; 1.0025x over previous
#include <cuda_runtime.h>
#include <math.h>

#define BB 2
#define NN 2048
#define CC 256
#define HH 8
#define DHH 32
#define TABW (2*NN-1)
#define SCALE 0.17677669529663687f  // 1/sqrt(32)

// ---- scratch (static device globals; no allocation allowed) ----
__device__ float g_q[BB*HH*NN*DHH];
__device__ float g_k[BB*HH*NN*DHH];
__device__ float g_v[BB*HH*NN*DHH];
__device__ float g_ctx[BB*NN*CC];
__device__ float g_tab[HH*TABW];
__device__ float g_pm[HH*NN];    // pos row max
__device__ float g_pinv[HH*NN];  // 1 / pos row sumexp
__device__ float g_m[BB*HH*NN];  // patch row max (scaled scores)
__device__ float g_l[BB*HH*NN];  // patch row sumexp

// ============================================================
// 1) positional logit table: tab[h][dd], dd = d + (N-1)
// ============================================================
__global__ void pos_tab_kernel(const float* __restrict__ Wpos,
                               const float* __restrict__ bpos) {
    int idx = blockIdx.x * blockDim.x + threadIdx.x;
    if (idx >= HH * TABW) return;
    int h  = idx / TABW;
    int dd = idx % TABW;
    float d = (float)(dd - (NN - 1));
    g_tab[idx] = Wpos[h] * d + Wpos[HH + h] * fabsf(d) + bpos[h];
}

// ============================================================
// 2) per (h, i): row max (analytic, piecewise-linear) + sumexp
//    one warp per row
// ============================================================
__global__ void pos_row_kernel() {
    int w    = blockIdx.x * 8 + (threadIdx.x >> 5);
    int lane = threadIdx.x & 31;
    int h = w / NN, i = w % NN;
    const float* tab = g_tab + h * TABW;
    // window d in [i-(N-1), i] always contains 0; linear on each side of 0
    float m = fmaxf(fmaxf(tab[i], tab[i + NN - 1]), tab[NN - 1]);
    float s = 0.f;
    for (int j = lane; j < NN; j += 32)
        s += __expf(tab[i + NN - 1 - j] - m);
    #pragma unroll
    for (int o = 16; o; o >>= 1) s += __shfl_xor_sync(0xffffffffu, s, o);
    if (lane == 0) { g_pm[h*NN + i] = m; g_pinv[h*NN + i] = 1.f / s; }
}

// ============================================================
// 3) QKV projection GEMM: [4096,256] x [256,768] -> scatter q/k/v
//    64x64 tile, 256 threads, 4x4 micro
// ============================================================
__global__ void qkv_gemm_kernel(const float* __restrict__ x,
                                const float* __restrict__ Wqk,
                                const float* __restrict__ Wv) {
    __shared__ float As[16][64];
    __shared__ float Bs[16][64];
    int tid = threadIdx.x;
    int ty = tid >> 4, tx = tid & 15;
    int m0 = blockIdx.x * 64;
    int n0 = blockIdx.y * 64;
    float acc[4][4] = {};
    int arow = tid >> 2, acol = (tid & 3) * 4;
    int brow = tid >> 4, bcol = (tid & 15) * 4;

    for (int k0 = 0; k0 < 256; k0 += 16) {
        float4 av = *(const float4*)&x[(m0 + arow) * 256 + k0 + acol];
        As[acol + 0][arow] = av.x; As[acol + 1][arow] = av.y;
        As[acol + 2][arow] = av.z; As[acol + 3][arow] = av.w;
        int gc = n0 + bcol;
        float4 bv;
        if (gc < 512) bv = *(const float4*)&Wqk[(k0 + brow) * 512 + gc];
        else          bv = *(const float4*)&Wv[(k0 + brow) * 256 + gc - 512];
        *(float4*)&Bs[brow][bcol] = bv;
        __syncthreads();
        #pragma unroll
        for (int kk = 0; kk < 16; kk++) {
            float4 a = *(float4*)&As[kk][4 * ty];
            float4 b = *(float4*)&Bs[kk][4 * tx];
            float aa[4] = {a.x, a.y, a.z, a.w};
            float bb[4] = {b.x, b.y, b.z, b.w};
            #pragma unroll
            for (int i = 0; i < 4; i++)
                #pragma unroll
                for (int j = 0; j < 4; j++)
                    acc[i][j] += aa[i] * bb[j];
        }
        __syncthreads();
    }
    #pragma unroll
    for (int i = 0; i < 4; i++) {
        int m = m0 + 4 * ty + i;
        int b = m >> 11, n = m & (NN - 1);
        #pragma unroll
        for (int j = 0; j < 4; j++) {
            int c = n0 + 4 * tx + j;
            float v = acc[i][j];
            if (c < 256) {
                int h = c >> 5, d = c & 31;
                g_q[((b * HH + h) * NN + n) * DHH + d] = v;
            } else if (c < 512) {
                int cc = c - 256; int h = cc >> 5, d = cc & 31;
                g_k[((b * HH + h) * NN + n) * DHH + d] = v;
            } else {
                int cc = c - 512; int h = cc >> 5, d = cc & 31;
                g_v[((b * HH + h) * NN + n) * DHH + d] = v;
            }
        }
    }
}

// ============================================================
// 4) Pass A: patch-softmax row max + sumexp (online over key tiles)
//    block = 64 q-rows of one (b,h); 256 threads as 16x16, 4x4 micro
// ============================================================
__global__ void attn_ml_kernel() {
    __shared__ float qs[32][64];  // [d][row], pre-scaled
    __shared__ float ks[32][64];  // [d][key]
    int tid = threadIdx.x;
    int ty = tid >> 4, tx = tid & 15;
    int qt = blockIdx.x, h = blockIdx.y, b = blockIdx.z;
    int bh = b * HH + h;
    const float* qg = g_q + (bh * NN + qt * 64) * DHH;
    const float* kg = g_k + bh * NN * DHH;

    #pragma unroll
    for (int r = 0; r < 8; r++) {
        int lin = tid + r * 256;
        qs[lin & 31][lin >> 5] = qg[lin] * SCALE;
    }
    float m[4], l[4];
    #pragma unroll
    for (int i = 0; i < 4; i++) { m[i] = -1e30f; l[i] = 0.f; }

    for (int kt = 0; kt < 32; kt++) {
        __syncthreads();
        #pragma unroll
        for (int r = 0; r < 8; r++) {
            int lin = tid + r * 256;
            ks[lin & 31][lin >> 5] = kg[kt * 64 * DHH + lin];
        }
        __syncthreads();
        float s[4][4] = {};
        #pragma unroll
        for (int d = 0; d < 32; d++) {
            float4 a  = *(float4*)&qs[d][4 * ty];
            float4 bv = *(float4*)&ks[d][4 * tx];
            float aa[4] = {a.x, a.y, a.z, a.w};
            float bb[4] = {bv.x, bv.y, bv.z, bv.w};
            #pragma unroll
            for (int i = 0; i < 4; i++)
                #pragma unroll
                for (int j = 0; j < 4; j++)
                    s[i][j] += aa[i] * bb[j];
        }
        #pragma unroll
        for (int i = 0; i < 4; i++) {
            float rm = fmaxf(fmaxf(s[i][0], s[i][1]), fmaxf(s[i][2], s[i][3]));
            #pragma unroll
            for (int o = 8; o; o >>= 1) rm = fmaxf(rm, __shfl_xor_sync(0xffffffffu, rm, o));
            float mn = fmaxf(m[i], rm);
            float rs = __expf(s[i][0] - mn) + __expf(s[i][1] - mn)
                     + __expf(s[i][2] - mn) + __expf(s[i][3] - mn);
            #pragma unroll
            for (int o = 8; o; o >>= 1) rs += __shfl_xor_sync(0xffffffffu, rs, o);
            l[i] = l[i] * __expf(m[i] - mn) + rs;
            m[i] = mn;
        }
    }
    if (tx == 0) {
        #pragma unroll
        for (int i = 0; i < 4; i++) {
            int row = bh * NN + qt * 64 + 4 * ty + i;
            g_m[row] = m[i];
            g_l[row] = l[i];
        }
    }
}

// ============================================================
// 5) Pass B: combined weights + P@V -> ctx [B,N,C]
// ============================================================
__global__ void attn_out_kernel(const float* __restrict__ gating) {
    __shared__ float qs[32][64];
    __shared__ float ks[32][64];
    __shared__ float vs[64][32];
    __shared__ float pT[64][66];   // [key][row], padded
    __shared__ float ts[128];      // pos-logit slice
    __shared__ float cm[64], cl1[64], pm[64], c2[64];

    int tid = threadIdx.x;
    int ty = tid >> 4, tx = tid & 15;
    int y2 = tid >> 3, x2 = tid & 7;
    int qt = blockIdx.x, h = blockIdx.y, b = blockIdx.z;
    int bh = b * HH + h;
    int q0 = qt * 64;
    const float* qg = g_q + (bh * NN + q0) * DHH;
    const float* kg = g_k + bh * NN * DHH;
    const float* vg = g_v + bh * NN * DHH;

    #pragma unroll
    for (int r = 0; r < 8; r++) {
        int lin = tid + r * 256;
        qs[lin & 31][lin >> 5] = qg[lin] * SCALE;
    }
    if (tid < 64) {
        int grow = q0 + tid;
        float gv = 1.f / (1.f + __expf(-gating[h]));
        cm[tid]  = g_m[bh * NN + grow];
        cl1[tid] = (1.f - gv) / g_l[bh * NN + grow];
        pm[tid]  = g_pm[h * NN + grow];
        c2[tid]  = gv * g_pinv[h * NN + grow];
    }
    float acc0[4] = {}, acc1[4] = {};

    for (int kt = 0; kt < 32; kt++) {
        int k0 = kt * 64;
        __syncthreads();
        #pragma unroll
        for (int r = 0; r < 8; r++) {
            int lin = tid + r * 256;
            ks[lin & 31][lin >> 5] = kg[k0 * DHH + lin];
            ((float*)vs)[lin]      = vg[k0 * DHH + lin];
        }
        if (tid < 127) ts[tid] = g_tab[h * TABW + (q0 - k0 + 1984) + tid];
        __syncthreads();

        float s[4][4] = {};
        #pragma unroll
        for (int d = 0; d < 32; d++) {
            float4 a  = *(float4*)&qs[d][4 * ty];
            float4 bv = *(float4*)&ks[d][4 * tx];
            float aa[4] = {a.x, a.y, a.z, a.w};
            float bb[4] = {bv.x, bv.y, bv.z, bv.w};
            #pragma unroll
            for (int i = 0; i < 4; i++)
                #pragma unroll
                for (int j = 0; j < 4; j++)
                    s[i][j] += aa[i] * bb[j];
        }
        #pragma unroll
        for (int i = 0; i < 4; i++) {
            int r = 4 * ty + i;
            float c1r = cl1[r], cmr = cm[r], c2r = c2[r], pmr = pm[r];
            #pragma unroll
            for (int j = 0; j < 4; j++) {
                int jl = 4 * tx + j;
                float w = c1r * __expf(s[i][j] - cmr)
                        + c2r * __expf(ts[r - jl + 63] - pmr);
                pT[jl][r] = w;
            }
        }
        __syncthreads();
        #pragma unroll 16
        for (int j = 0; j < 64; j++) {
            float a0 = pT[j][2 * y2], a1 = pT[j][2 * y2 + 1];
            float4 bv = *(float4*)&vs[j][4 * x2];
            acc0[0] += a0 * bv.x; acc0[1] += a0 * bv.y;
            acc0[2] += a0 * bv.z; acc0[3] += a0 * bv.w;
            acc1[0] += a1 * bv.x; acc1[1] += a1 * bv.y;
            acc1[2] += a1 * bv.z; acc1[3] += a1 * bv.w;
        }
    }
    int row = q0 + 2 * y2;
    int col = h * 32 + 4 * x2;
    float* o0 = &g_ctx[(b * NN + row) * CC + col];
    *(float4*)o0        = make_float4(acc0[0], acc0[1], acc0[2], acc0[3]);
    *(float4*)(o0 + CC) = make_float4(acc1[0], acc1[1], acc1[2], acc1[3]);
}

// ============================================================
// 6) Output projection: ctx [4096,256] x W_proj [256,256] + b -> out
// ============================================================
__global__ void proj_gemm_kernel(const float* __restrict__ Wp,
                                 const float* __restrict__ bp,
                                 float* __restrict__ out) {
    __shared__ float As[16][64];
    __shared__ float Bs[16][64];
    int tid = threadIdx.x;
    int ty = tid >> 4, tx = tid & 15;
    int m0 = blockIdx.x * 64;
    int n0 = blockIdx.y * 64;
    float acc[4][4] = {};
    int arow = tid >> 2, acol = (tid & 3) * 4;
    int brow = tid >> 4, bcol = (tid & 15) * 4;

    for (int k0 = 0; k0 < 256; k0 += 16) {
        float4 av = *(const float4*)&g_ctx[(m0 + arow) * 256 + k0 + acol];
        As[acol + 0][arow] = av.x; As[acol + 1][arow] = av.y;
        As[acol + 2][arow] = av.z; As[acol + 3][arow] = av.w;
        float4 bv = *(const float4*)&Wp[(k0 + brow) * 256 + n0 + bcol];
        *(float4*)&Bs[brow][bcol] = bv;
        __syncthreads();
        #pragma unroll
        for (int kk = 0; kk < 16; kk++) {
            float4 a = *(float4*)&As[kk][4 * ty];
            float4 b = *(float4*)&Bs[kk][4 * tx];
            float aa[4] = {a.x, a.y, a.z, a.w};
            float bb[4] = {b.x, b.y, b.z, b.w};
            #pragma unroll
            for (int i = 0; i < 4; i++)
                #pragma unroll
                for (int j = 0; j < 4; j++)
                    acc[i][j] += aa[i] * bb[j];
        }
        __syncthreads();
    }
    #pragma unroll
    for (int i = 0; i < 4; i++) {
        int m = m0 + 4 * ty + i;
        #pragma unroll
        for (int j = 0; j < 4; j++) {
            int c = n0 + 4 * tx + j;
            out[m * 256 + c] = acc[i][j] + bp[c];
        }
    }
}

// ============================================================
extern "C" void kernel_launch(void* const* d_in, const int* in_sizes, int n_in,
                              void* d_out, int out_size) {
    const float* x     = (const float*)d_in[0];
    const float* Wqk   = (const float*)d_in[1];
    const float* Wv    = (const float*)d_in[2];
    const float* Wproj = (const float*)d_in[3];
    const float* bproj = (const float*)d_in[4];
    const float* Wpos  = (const float*)d_in[5];
    const float* bpos  = (const float*)d_in[6];
    const float* gate  = (const float*)d_in[7];
    float* out = (float*)d_out;

    pos_tab_kernel<<<(HH * TABW + 255) / 256, 256>>>(Wpos, bpos);
    pos_row_kernel<<<HH * NN / 8, 256>>>();
    qkv_gemm_kernel<<<dim3(BB * NN / 64, 12), 256>>>(x, Wqk, Wv);
    attn_ml_kernel<<<dim3(NN / 64, HH, BB), 256>>>();
    attn_out_kernel<<<dim3(NN / 64, HH, BB), 256>>>(gate);
    proj_gemm_kernel<<<dim3(BB * NN / 64, 4), 256>>>(Wproj, bproj, out);
}

// round 3
// speedup vs baseline: 1.9078x; 1.9030x over previous
#include <cuda_runtime.h>
#include <math.h>

#define BB 2
#define NN 2048
#define CC 256
#define HH 8
#define DHH 32
#define TABW (2*NN-1)
#define SCALE 0.17677669529663687f  // 1/sqrt(32)

typedef unsigned long long u64;

// ---- scratch ----
__device__ float g_qT[BB*HH*DHH*NN];   // [bh][d][n], pre-scaled
__device__ float g_kT[BB*HH*DHH*NN];   // [bh][d][n]
__device__ float g_v [BB*HH*NN*DHH];   // [bh][n][d]
__device__ float g_ctx[BB*NN*CC];
__device__ float g_tab[HH*TABW];
__device__ float g_pm[HH*NN];
__device__ float g_pinv[HH*NN];
__device__ float g_l[BB*HH*NN];

// ---- f32x2 helpers ----
__device__ __forceinline__ void fma2(u64 &acc, u64 a, u64 b) {
    asm("fma.rn.f32x2 %0, %1, %2, %0;" : "+l"(acc) : "l"(a), "l"(b));
}
__device__ __forceinline__ u64 dup2(float x) {
    u64 r; asm("mov.b64 %0, {%1, %1};" : "=l"(r) : "f"(x)); return r;
}
__device__ __forceinline__ float2 unpack2(u64 v) {
    float2 r; asm("mov.b64 {%0, %1}, %2;" : "=f"(r.x), "=f"(r.y) : "l"(v)); return r;
}

// ============================================================
// 1) positional logit table
// ============================================================
__global__ void pos_tab_kernel(const float* __restrict__ Wpos,
                               const float* __restrict__ bpos) {
    int idx = blockIdx.x * blockDim.x + threadIdx.x;
    if (idx >= HH * TABW) return;
    int h = idx / TABW, dd = idx % TABW;
    float d = (float)(dd - (NN - 1));
    g_tab[idx] = Wpos[h] * d + Wpos[HH + h] * fabsf(d) + bpos[h];
}

// ============================================================
// 2) pos softmax row stats (analytic max)
// ============================================================
__global__ void pos_row_kernel() {
    int w = blockIdx.x * 8 + (threadIdx.x >> 5);
    int lane = threadIdx.x & 31;
    int h = w / NN, i = w % NN;
    const float* tab = g_tab + h * TABW;
    float m = fmaxf(fmaxf(tab[i], tab[i + NN - 1]), tab[NN - 1]);
    float s = 0.f;
    for (int j = lane; j < NN; j += 32)
        s += __expf(tab[i + NN - 1 - j] - m);
    #pragma unroll
    for (int o = 16; o; o >>= 1) s += __shfl_xor_sync(0xffffffffu, s, o);
    if (lane == 0) { g_pm[h*NN + i] = m; g_pinv[h*NN + i] = 1.f / s; }
}

// ============================================================
// 3) QKV GEMM -> scatter into g_qT (scaled), g_kT, g_v
// ============================================================
__global__ void qkv_gemm_kernel(const float* __restrict__ x,
                                const float* __restrict__ Wqk,
                                const float* __restrict__ Wv) {
    __shared__ float As[16][64];
    __shared__ float Bs[16][64];
    int tid = threadIdx.x;
    int ty = tid >> 4, tx = tid & 15;
    int m0 = blockIdx.x * 64, n0 = blockIdx.y * 64;
    float acc[4][4] = {};
    int arow = tid >> 2, acol = (tid & 3) * 4;
    int brow = tid >> 4, bcol = (tid & 15) * 4;

    for (int k0 = 0; k0 < 256; k0 += 16) {
        float4 av = *(const float4*)&x[(m0 + arow) * 256 + k0 + acol];
        As[acol + 0][arow] = av.x; As[acol + 1][arow] = av.y;
        As[acol + 2][arow] = av.z; As[acol + 3][arow] = av.w;
        int gc = n0 + bcol;
        float4 bv;
        if (gc < 512) bv = *(const float4*)&Wqk[(k0 + brow) * 512 + gc];
        else          bv = *(const float4*)&Wv[(k0 + brow) * 256 + gc - 512];
        *(float4*)&Bs[brow][bcol] = bv;
        __syncthreads();
        #pragma unroll
        for (int kk = 0; kk < 16; kk++) {
            float4 a = *(float4*)&As[kk][4 * ty];
            float4 b = *(float4*)&Bs[kk][4 * tx];
            float aa[4] = {a.x, a.y, a.z, a.w};
            float bb[4] = {b.x, b.y, b.z, b.w};
            #pragma unroll
            for (int i = 0; i < 4; i++)
                #pragma unroll
                for (int j = 0; j < 4; j++)
                    acc[i][j] += aa[i] * bb[j];
        }
        __syncthreads();
    }
    #pragma unroll
    for (int i = 0; i < 4; i++) {
        int m = m0 + 4 * ty + i;
        int b = m >> 11, n = m & (NN - 1);
        #pragma unroll
        for (int j = 0; j < 4; j++) {
            int c = n0 + 4 * tx + j;
            float v = acc[i][j];
            if (c < 256) {
                int h = c >> 5, d = c & 31;
                g_qT[((b * HH + h) * DHH + d) * NN + n] = v * SCALE;
            } else if (c < 512) {
                int cc = c - 256; int h = cc >> 5, d = cc & 31;
                g_kT[((b * HH + h) * DHH + d) * NN + n] = v;
            } else {
                int cc = c - 512; int h = cc >> 5, d = cc & 31;
                g_v[((b * HH + h) * NN + n) * DHH + d] = v;
            }
        }
    }
}

// ============================================================
// helper: load a [32][128] transposed tile (g_?T layout) into smem pad-132
// ============================================================
__device__ __forceinline__ void load_tile_T132(float (*dst)[132],
                                               const float* __restrict__ src,
                                               int n0, int tid) {
    #pragma unroll
    for (int r = 0; r < 4; r++) {
        int idx = tid + r * 256;          // 0..1023
        int c  = idx & 15;
        int d  = (idx >> 4) & 31;
        int h2 = idx >> 9;                // 0..1
        int col = 4 * (c + 16 * h2);
        float4 v = *(const float4*)&src[d * NN + n0 + col];
        *(float4*)&dst[d][col] = v;
    }
}

// ============================================================
// 4) Pass A: l_i = sum_j exp(s_ij), m=0.  128q x 128k tiles, f32x2.
// ============================================================
__global__ void __launch_bounds__(256) attn_l_kernel() {
    __shared__ float qs[32][132];
    __shared__ float ks[32][132];
    int tid = threadIdx.x;
    int ty = tid >> 4, tx = tid & 15;
    int qt = blockIdx.x, h = blockIdx.y, b = blockIdx.z;
    int bh = b * HH + h;
    int q0 = qt * 128;
    const float* qg = g_qT + bh * DHH * NN;
    const float* kg = g_kT + bh * DHH * NN;

    load_tile_T132(qs, qg, q0, tid);
    float l[8] = {};

    for (int kt = 0; kt < 16; kt++) {
        __syncthreads();
        load_tile_T132(ks, kg, kt * 128, tid);
        __syncthreads();
        u64 acc[4][8] = {};
        #pragma unroll
        for (int d = 0; d < 32; d++) {
            ulonglong2 a0 = *(const ulonglong2*)&qs[d][8 * ty];
            ulonglong2 a1 = *(const ulonglong2*)&qs[d][8 * ty + 4];
            float4 b0 = *(const float4*)&ks[d][8 * tx];
            float4 b1 = *(const float4*)&ks[d][8 * tx + 4];
            u64 ap[4] = {a0.x, a0.y, a1.x, a1.y};
            u64 bd[8] = {dup2(b0.x), dup2(b0.y), dup2(b0.z), dup2(b0.w),
                         dup2(b1.x), dup2(b1.y), dup2(b1.z), dup2(b1.w)};
            #pragma unroll
            for (int p = 0; p < 4; p++)
                #pragma unroll
                for (int j = 0; j < 8; j++)
                    fma2(acc[p][j], ap[p], bd[j]);
        }
        #pragma unroll
        for (int p = 0; p < 4; p++)
            #pragma unroll
            for (int j = 0; j < 8; j++) {
                float2 s = unpack2(acc[p][j]);
                l[2*p]   += __expf(s.x);
                l[2*p+1] += __expf(s.y);
            }
    }
    #pragma unroll
    for (int o = 8; o; o >>= 1)
        #pragma unroll
        for (int r = 0; r < 8; r++)
            l[r] += __shfl_xor_sync(0xffffffffu, l[r], o);
    if (tx == 0)
        #pragma unroll
        for (int r = 0; r < 8; r++)
            g_l[bh * NN + q0 + 8 * ty + r] = l[r];
}

// ============================================================
// 5) Pass B: combined weights + P@V.  128q x 32k tiles, f32x2.
// ============================================================
__global__ void __launch_bounds__(256) attn_out_kernel(const float* __restrict__ gating) {
    __shared__ float qs[32][132];
    __shared__ float ks[32][36];
    __shared__ float vs[32][36];
    __shared__ float pT[32][132];   // [k][q-row]
    __shared__ float ts[160];
    __shared__ float c1[128], c2[128], pm[128];

    int tid = threadIdx.x;
    int ty = tid >> 4, tx = tid & 15;
    int qt = blockIdx.x, h = blockIdx.y, b = blockIdx.z;
    int bh = b * HH + h;
    int q0 = qt * 128;
    const float* qg = g_qT + bh * DHH * NN;
    const float* kg = g_kT + bh * DHH * NN;
    const float* vg = g_v  + bh * NN * DHH;

    load_tile_T132(qs, qg, q0, tid);
    if (tid < 128) {
        int row = q0 + tid;
        float gv = 1.f / (1.f + __expf(-gating[h]));
        c1[tid] = (1.f - gv) / g_l[bh * NN + row];
        c2[tid] = gv * g_pinv[h * NN + row];
        pm[tid] = g_pm[h * NN + row];
    }
    int dx = tx & 7, ks2 = tx >> 3;
    u64 oacc[4][4] = {};

    for (int kt = 0; kt < 64; kt++) {
        int k0 = kt * 32;
        __syncthreads();
        {   // load ks (transposed source), vs (natural), ts
            int c = tid & 7, d = tid >> 3;
            *(float4*)&ks[d][4 * c] = *(const float4*)&kg[d * NN + k0 + 4 * c];
            int vrow = tid >> 3, vdq = tid & 7;
            *(float4*)&vs[vrow][4 * vdq] = *(const float4*)&vg[(k0 + vrow) * DHH + 4 * vdq];
            if (tid < 159) ts[tid] = g_tab[h * TABW + q0 - k0 + 2016 + tid];
        }
        __syncthreads();
        // QK: 8q x 2k per thread (k cols tx, tx+16)
        u64 sacc[4][2] = {};
        #pragma unroll
        for (int d = 0; d < 32; d++) {
            ulonglong2 a0 = *(const ulonglong2*)&qs[d][8 * ty];
            ulonglong2 a1 = *(const ulonglong2*)&qs[d][8 * ty + 4];
            u64 ap[4] = {a0.x, a0.y, a1.x, a1.y};
            u64 bd0 = dup2(ks[d][tx]);
            u64 bd1 = dup2(ks[d][tx + 16]);
            #pragma unroll
            for (int p = 0; p < 4; p++) {
                fma2(sacc[p][0], ap[p], bd0);
                fma2(sacc[p][1], ap[p], bd1);
            }
        }
        // combined weights -> pT
        #pragma unroll
        for (int p = 0; p < 4; p++) {
            int i0 = 8 * ty + 2 * p;
            #pragma unroll
            for (int j = 0; j < 2; j++) {
                int kc = tx + 16 * j;
                float2 s = unpack2(sacc[p][j]);
                float w0 = c1[i0]   * __expf(s.x) + c2[i0]   * __expf(ts[i0     - kc + 31] - pm[i0]);
                float w1 = c1[i0+1] * __expf(s.y) + c2[i0+1] * __expf(ts[i0 + 1 - kc + 31] - pm[i0+1]);
                pT[kc][i0]     = w0;
                pT[kc][i0 + 1] = w1;
            }
        }
        __syncthreads();
        // PV: 8q x 4d per thread, 2-way split over k
        #pragma unroll
        for (int kk = 0; kk < 16; kk++) {
            int k = 2 * kk + ks2;
            ulonglong2 a0 = *(const ulonglong2*)&pT[k][8 * ty];
            ulonglong2 a1 = *(const ulonglong2*)&pT[k][8 * ty + 4];
            u64 ap[4] = {a0.x, a0.y, a1.x, a1.y};
            float4 bv = *(const float4*)&vs[k][4 * dx];
            u64 bd[4] = {dup2(bv.x), dup2(bv.y), dup2(bv.z), dup2(bv.w)};
            #pragma unroll
            for (int p = 0; p < 4; p++)
                #pragma unroll
                for (int j = 0; j < 4; j++)
                    fma2(oacc[p][j], ap[p], bd[j]);
        }
    }
    // reduce split-k partners (lanes differ by bit 3) and store
    #pragma unroll
    for (int p = 0; p < 4; p++)
        #pragma unroll
        for (int j = 0; j < 4; j++) {
            float2 v = unpack2(oacc[p][j]);
            v.x += __shfl_xor_sync(0xffffffffu, v.x, 8);
            v.y += __shfl_xor_sync(0xffffffffu, v.y, 8);
            if (tx < 8) {
                int row = q0 + 8 * ty + 2 * p;
                int col = h * 32 + 4 * tx + j;
                g_ctx[(b * NN + row) * CC + col]     = v.x;
                g_ctx[(b * NN + row + 1) * CC + col] = v.y;
            }
        }
}

// ============================================================
// 6) Output projection
// ============================================================
__global__ void proj_gemm_kernel(const float* __restrict__ Wp,
                                 const float* __restrict__ bp,
                                 float* __restrict__ out) {
    __shared__ float As[16][64];
    __shared__ float Bs[16][64];
    int tid = threadIdx.x;
    int ty = tid >> 4, tx = tid & 15;
    int m0 = blockIdx.x * 64, n0 = blockIdx.y * 64;
    float acc[4][4] = {};
    int arow = tid >> 2, acol = (tid & 3) * 4;
    int brow = tid >> 4, bcol = (tid & 15) * 4;

    for (int k0 = 0; k0 < 256; k0 += 16) {
        float4 av = *(const float4*)&g_ctx[(m0 + arow) * 256 + k0 + acol];
        As[acol + 0][arow] = av.x; As[acol + 1][arow] = av.y;
        As[acol + 2][arow] = av.z; As[acol + 3][arow] = av.w;
        float4 bv = *(const float4*)&Wp[(k0 + brow) * 256 + n0 + bcol];
        *(float4*)&Bs[brow][bcol] = bv;
        __syncthreads();
        #pragma unroll
        for (int kk = 0; kk < 16; kk++) {
            float4 a = *(float4*)&As[kk][4 * ty];
            float4 b = *(float4*)&Bs[kk][4 * tx];
            float aa[4] = {a.x, a.y, a.z, a.w};
            float bb[4] = {b.x, b.y, b.z, b.w};
            #pragma unroll
            for (int i = 0; i < 4; i++)
                #pragma unroll
                for (int j = 0; j < 4; j++)
                    acc[i][j] += aa[i] * bb[j];
        }
        __syncthreads();
    }
    #pragma unroll
    for (int i = 0; i < 4; i++) {
        int m = m0 + 4 * ty + i;
        #pragma unroll
        for (int j = 0; j < 4; j++) {
            int c = n0 + 4 * tx + j;
            out[m * 256 + c] = acc[i][j] + bp[c];
        }
    }
}

// ============================================================
extern "C" void kernel_launch(void* const* d_in, const int* in_sizes, int n_in,
                              void* d_out, int out_size) {
    const float* x     = (const float*)d_in[0];
    const float* Wqk   = (const float*)d_in[1];
    const float* Wv    = (const float*)d_in[2];
    const float* Wproj = (const float*)d_in[3];
    const float* bproj = (const float*)d_in[4];
    const float* Wpos  = (const float*)d_in[5];
    const float* bpos  = (const float*)d_in[6];
    const float* gate  = (const float*)d_in[7];
    float* out = (float*)d_out;

    pos_tab_kernel<<<(HH * TABW + 255) / 256, 256>>>(Wpos, bpos);
    pos_row_kernel<<<HH * NN / 8, 256>>>();
    qkv_gemm_kernel<<<dim3(BB * NN / 64, 12), 256>>>(x, Wqk, Wv);
    attn_l_kernel<<<dim3(NN / 128, HH, BB), 256>>>();
    attn_out_kernel<<<dim3(NN / 128, HH, BB), 256>>>(gate);
    proj_gemm_kernel<<<dim3(BB * NN / 64, 4), 256>>>(Wproj, bproj, out);
}